// round 1
// baseline (speedup 1.0000x reference)
#include <cuda_runtime.h>

#define Bsz 256
#define Hd  512
#define N3  1536
#define KTOT 1024

// Scratch (no allocs allowed)
__device__ float g_proj[Bsz * N3];   // [B, 3H]: [u_gate | r | x_emb]
__device__ float g_Rh[Bsz * Hd];     // R @ hidden
__device__ float g_hn[Bsz * Hd];     // assoc @ Rh

__device__ __forceinline__ void ffma2(unsigned long long &acc,
                                      unsigned long long a,
                                      unsigned long long b) {
    asm("fma.rn.f32x2 %0, %1, %2, %3;" : "=l"(acc) : "l"(a), "l"(b), "l"(acc));
}

__device__ __forceinline__ unsigned long long bcast2(float v) {
    unsigned long long r;
    unsigned u = __float_as_uint(v);
    asm("mov.b64 %0, {%1, %1};" : "=l"(r) : "r"(u));
    return r;
}

// ---------------------------------------------------------------------------
// Kernel 1: proj = [inputs|hidden] @ [W_ih|W_hh]^T + b_ih + b_hh
// M=256, N=1536, K=1024 fp32 GEMM. BM=BN=64, BK=32, 256 thr, 4x4 thread tile,
// inner product via packed f32x2 FMA (2 MACs / instr).
// ---------------------------------------------------------------------------
__global__ __launch_bounds__(256) void gemm_proj_kernel(
    const float* __restrict__ inputs, const float* __restrict__ hidden,
    const float* __restrict__ W_ih,   const float* __restrict__ b_ih,
    const float* __restrict__ W_hh,   const float* __restrict__ b_hh)
{
    const int BM = 64, BN = 64, BK = 32;
    __shared__ __align__(16) float As[BK][BM + 4];
    __shared__ __align__(16) float Bs[BK][BN + 4];

    const int tid = threadIdx.x;
    const int bm  = blockIdx.y * BM;   // batch rows
    const int bn  = blockIdx.x * BN;   // output cols (3H)
    const int tx  = tid & 15;          // n
    const int ty  = tid >> 4;          // m

    unsigned long long acc[2][4];
    #pragma unroll
    for (int p = 0; p < 2; p++)
        #pragma unroll
        for (int n = 0; n < 4; n++) acc[p][n] = 0ULL;  // (+0.f, +0.f)

    for (int k0 = 0; k0 < KTOT; k0 += BK) {
        // Load 64x32 A tile and 64x32 B tile, stored transposed [k][m]/[k][n].
        #pragma unroll
        for (int l = 0; l < 2; l++) {
            int f   = tid + l * 256;
            int row = f >> 3;
            int kc  = (f & 7) << 2;
            int gk  = k0 + kc;          // uniform side of the 512 split per tile
            float4 va, vb;
            if (gk < 512) {
                va = *(const float4*)(inputs + (size_t)(bm + row) * 512 + gk);
                vb = *(const float4*)(W_ih   + (size_t)(bn + row) * 512 + gk);
            } else {
                va = *(const float4*)(hidden + (size_t)(bm + row) * 512 + gk - 512);
                vb = *(const float4*)(W_hh   + (size_t)(bn + row) * 512 + gk - 512);
            }
            As[kc + 0][row] = va.x; As[kc + 1][row] = va.y;
            As[kc + 2][row] = va.z; As[kc + 3][row] = va.w;
            Bs[kc + 0][row] = vb.x; Bs[kc + 1][row] = vb.y;
            Bs[kc + 2][row] = vb.z; Bs[kc + 3][row] = vb.w;
        }
        __syncthreads();

        #pragma unroll
        for (int kk = 0; kk < BK; kk++) {
            union { float4 f; unsigned long long u[2]; } a, bv;
            a.f  = *(const float4*)&As[kk][ty << 2];
            bv.f = *(const float4*)&Bs[kk][tx << 2];
            unsigned long long bb0 = bcast2(bv.f.x);
            unsigned long long bb1 = bcast2(bv.f.y);
            unsigned long long bb2 = bcast2(bv.f.z);
            unsigned long long bb3 = bcast2(bv.f.w);
            ffma2(acc[0][0], a.u[0], bb0); ffma2(acc[1][0], a.u[1], bb0);
            ffma2(acc[0][1], a.u[0], bb1); ffma2(acc[1][1], a.u[1], bb1);
            ffma2(acc[0][2], a.u[0], bb2); ffma2(acc[1][2], a.u[1], bb2);
            ffma2(acc[0][3], a.u[0], bb3); ffma2(acc[1][3], a.u[1], bb3);
        }
        __syncthreads();
    }

    // Epilogue: +bias, write proj
    #pragma unroll
    for (int n = 0; n < 4; n++) {
        int j = bn + (tx << 2) + n;
        float bias = b_ih[j] + b_hh[j];
        #pragma unroll
        for (int p = 0; p < 2; p++) {
            float lo = __uint_as_float((unsigned)(acc[p][n] & 0xffffffffULL));
            float hi = __uint_as_float((unsigned)(acc[p][n] >> 32));
            int m0 = bm + (ty << 2) + 2 * p;
            g_proj[(size_t)m0 * N3 + j]       = lo + bias;
            g_proj[(size_t)(m0 + 1) * N3 + j] = hi + bias;
        }
    }
}

// ---------------------------------------------------------------------------
// Kernel 2: per batch row: dot products -> alpha, beta;  Rh = h + a*x + b*r
//   R h = h + [(c-1)uh - s*vh] u + [(c-1)vh + s*uh] v,
//   u = x/nx, v = (r - g*x)/nv, g = (x.r)/nx^2
// ---------------------------------------------------------------------------
__global__ __launch_bounds__(128) void vectors_kernel(const float* __restrict__ hidden)
{
    const int b = blockIdx.x, t = threadIdx.x;
    const float* base = g_proj + (size_t)b * N3;
    float4 x = ((const float4*)(base + 2 * Hd))[t];   // x_emb
    float4 r = ((const float4*)(base + Hd))[t];       // r
    float4 h = ((const float4*)(hidden + (size_t)b * Hd))[t];

    float vals[5];
    vals[0] = x.x * x.x + x.y * x.y + x.z * x.z + x.w * x.w;  // sxx
    vals[1] = r.x * r.x + r.y * r.y + r.z * r.z + r.w * r.w;  // srr
    vals[2] = x.x * r.x + x.y * r.y + x.z * r.z + x.w * r.w;  // sxr
    vals[3] = x.x * h.x + x.y * h.y + x.z * h.z + x.w * h.w;  // sxh
    vals[4] = r.x * h.x + r.y * h.y + r.z * h.z + r.w * h.w;  // srh

    __shared__ float red[5][4];
    __shared__ float s_ab[2];
    int lane = t & 31, w = t >> 5;
    #pragma unroll
    for (int i = 0; i < 5; i++) {
        float v = vals[i];
        #pragma unroll
        for (int o = 16; o; o >>= 1) v += __shfl_down_sync(0xffffffffu, v, o);
        if (!lane) red[i][w] = v;
    }
    __syncthreads();
    if (t == 0) {
        float S[5];
        #pragma unroll
        for (int i = 0; i < 5; i++)
            S[i] = red[i][0] + red[i][1] + red[i][2] + red[i][3];
        const float eps = 1e-12f;
        float nx = fmaxf(sqrtf(S[0]), eps);
        float nr = fmaxf(sqrtf(S[1]), eps);
        float c  = S[2] / (nx * nr);
        float s  = sqrtf(fmaxf(1.0f - c * c, 0.0f));
        float ur = S[2] / nx;           // u . r
        float g  = ur / nx;             // coeff of x in v_unnorm
        float vn2 = S[1] - 2.0f * g * S[2] + g * g * S[0];
        float nv = fmaxf(sqrtf(fmaxf(vn2, 0.0f)), eps);
        float uh = S[3] / nx;
        float vh = (S[4] - g * S[3]) / nv;
        float P = (c - 1.0f) * uh - s * vh;
        float Q = (c - 1.0f) * vh + s * uh;
        s_ab[0] = P / nx - Q * g / nv;  // alpha (on x)
        s_ab[1] = Q / nv;               // beta  (on r)
    }
    __syncthreads();
    float al = s_ab[0], be = s_ab[1];
    float4 o;
    o.x = h.x + al * x.x + be * r.x;
    o.y = h.y + al * x.y + be * r.y;
    o.z = h.z + al * x.z + be * r.z;
    o.w = h.w + al * x.w + be * r.w;
    ((float4*)(g_Rh + (size_t)b * Hd))[t] = o;
}

// ---------------------------------------------------------------------------
// Kernel 3: hn[b,i] = assoc[b,i,:] . Rh[b,:]   (HBM-bound, 256 MB single read)
// grid (32, 256), 256 thr = 8 warps, 2 rows/warp, Rh cached in smem.
// ---------------------------------------------------------------------------
__global__ __launch_bounds__(256) void matvec_kernel(const float* __restrict__ assoc)
{
    __shared__ float sRh[Hd];
    const int b = blockIdx.y;
    const int warp = threadIdx.x >> 5, lane = threadIdx.x & 31;

    for (int i = threadIdx.x; i < Hd; i += 256)
        sRh[i] = g_Rh[(size_t)b * Hd + i];
    __syncthreads();

    #pragma unroll
    for (int rr = 0; rr < 2; rr++) {
        int row = blockIdx.x * 16 + warp * 2 + rr;
        const float4* p = (const float4*)(assoc + ((size_t)b * Hd + row) * Hd);
        float sum = 0.0f;
        #pragma unroll
        for (int it = 0; it < 4; it++) {
            float4 v = p[lane + it * 32];
            int j = (lane + it * 32) << 2;
            sum += v.x * sRh[j] + v.y * sRh[j + 1] + v.z * sRh[j + 2] + v.w * sRh[j + 3];
        }
        #pragma unroll
        for (int o = 16; o; o >>= 1) sum += __shfl_down_sync(0xffffffffu, sum, o);
        if (!lane) g_hn[(size_t)b * Hd + row] = sum;
    }
}

// ---------------------------------------------------------------------------
// Kernel 4: pre = ug*h + (1-ug)*relu(hn + x);  out = pre / max(||pre||, eps)
// ---------------------------------------------------------------------------
__global__ __launch_bounds__(128) void finalize_kernel(
    const float* __restrict__ hidden, float* __restrict__ out)
{
    const int b = blockIdx.x, t = threadIdx.x;
    const float* base = g_proj + (size_t)b * N3;
    float4 ug = ((const float4*)base)[t];
    float4 x  = ((const float4*)(base + 2 * Hd))[t];
    float4 h  = ((const float4*)(hidden + (size_t)b * Hd))[t];
    float4 hn = ((const float4*)(g_hn + (size_t)b * Hd))[t];

    float4 pre;
    pre.x = ug.x * h.x + (1.0f - ug.x) * fmaxf(hn.x + x.x, 0.0f);
    pre.y = ug.y * h.y + (1.0f - ug.y) * fmaxf(hn.y + x.y, 0.0f);
    pre.z = ug.z * h.z + (1.0f - ug.z) * fmaxf(hn.z + x.z, 0.0f);
    pre.w = ug.w * h.w + (1.0f - ug.w) * fmaxf(hn.w + x.w, 0.0f);

    float ss = pre.x * pre.x + pre.y * pre.y + pre.z * pre.z + pre.w * pre.w;
    int lane = t & 31, w = t >> 5;
    #pragma unroll
    for (int o = 16; o; o >>= 1) ss += __shfl_down_sync(0xffffffffu, ss, o);
    __shared__ float red[4];
    __shared__ float s_inv;
    if (!lane) red[w] = ss;
    __syncthreads();
    if (t == 0) {
        float n = sqrtf(red[0] + red[1] + red[2] + red[3]);
        s_inv = 1.0f / fmaxf(n, 1e-12f);
    }
    __syncthreads();
    float inv = s_inv;
    float4 o4;
    o4.x = pre.x * inv; o4.y = pre.y * inv; o4.z = pre.z * inv; o4.w = pre.w * inv;
    ((float4*)out)[b * (Hd / 4) + t] = o4;
}

extern "C" void kernel_launch(void* const* d_in, const int* in_sizes, int n_in,
                              void* d_out, int out_size)
{
    const float* inputs = (const float*)d_in[0];
    const float* hidden = (const float*)d_in[1];
    const float* assoc  = (const float*)d_in[2];
    const float* W_ih   = (const float*)d_in[3];
    const float* b_ih   = (const float*)d_in[4];
    const float* W_hh   = (const float*)d_in[5];
    const float* b_hh   = (const float*)d_in[6];
    float* out = (float*)d_out;

    dim3 g1(N3 / 64, Bsz / 64);                 // 24 x 4 = 96 CTAs
    gemm_proj_kernel<<<g1, 256>>>(inputs, hidden, W_ih, b_ih, W_hh, b_hh);
    vectors_kernel<<<Bsz, 128>>>(hidden);
    matvec_kernel<<<dim3(Hd / 16, Bsz), 256>>>(assoc);
    finalize_kernel<<<Bsz, 128>>>(hidden, out);
}

// round 4
// speedup vs baseline: 1.4806x; 1.4806x over previous
#include <cuda_runtime.h>
#include <cuda_bf16.h>
#include <cstdint>

#define Bsz 256
#define Hd  512
#define N3  1536
#define KTOT 1024

// ---------------- scratch (no allocs allowed) ----------------
__device__ float g_proj[Bsz * N3];   // [B, 3H]: [u_gate | r | x_emb]
__device__ float g_Rh[Bsz * Hd];     // R @ hidden
__device__ float g_hn[Bsz * Hd];     // assoc @ Rh
__device__ __nv_bfloat16 g_Ahi[Bsz * KTOT];
__device__ __nv_bfloat16 g_Alo[Bsz * KTOT];
__device__ __nv_bfloat16 g_Bhi[N3 * KTOT];
__device__ __nv_bfloat16 g_Blo[N3 * KTOT];

__device__ __forceinline__ uint32_t smem_to_u32(const void* p) {
    uint32_t a;
    asm("{ .reg .u64 t; cvta.to.shared.u64 t, %1; cvt.u32.u64 %0, t; }"
        : "=r"(a) : "l"(p));
    return a;
}
__device__ __forceinline__ void cp16(uint32_t s, const void* g) {
    asm volatile("cp.async.cg.shared.global [%0], [%1], 16;"
                 :: "r"(s), "l"(g) : "memory");
}
__device__ __forceinline__ void ldsm_x4(uint32_t* r, uint32_t addr) {
    asm volatile("ldmatrix.sync.aligned.m8n8.x4.shared.b16 {%0,%1,%2,%3}, [%4];"
                 : "=r"(r[0]), "=r"(r[1]), "=r"(r[2]), "=r"(r[3]) : "r"(addr));
}
__device__ __forceinline__ void mma_bf16(float* c, const uint32_t* a, const uint32_t* b) {
    asm volatile(
        "mma.sync.aligned.m16n8k16.row.col.f32.bf16.bf16.f32 "
        "{%0,%1,%2,%3}, {%4,%5,%6,%7}, {%8,%9}, {%0,%1,%2,%3};"
        : "+f"(c[0]), "+f"(c[1]), "+f"(c[2]), "+f"(c[3])
        : "r"(a[0]), "r"(a[1]), "r"(a[2]), "r"(a[3]), "r"(b[0]), "r"(b[1]));
}

// swizzled byte offset within a 64-row x 64-byte tile (4KB)
__device__ __forceinline__ uint32_t sw_off(int row, int chunk) {
    return (uint32_t)(row * 64 + ((chunk ^ ((row >> 1) & 3)) << 4));
}

// ---------------------------------------------------------------------------
// Kernel 0: fp32 -> (hi, lo) bf16 split of A=[inputs|hidden] and B=[W_ih|W_hh]
// ---------------------------------------------------------------------------
__global__ __launch_bounds__(256) void convert_kernel(
    const float* __restrict__ inputs, const float* __restrict__ hidden,
    const float* __restrict__ W_ih,   const float* __restrict__ W_hh)
{
    const int A_N = Bsz * KTOT / 4;          // 65536
    const int B_N = N3 * KTOT / 4;           // 393216
    int idx = blockIdx.x * blockDim.x + threadIdx.x;
    if (idx >= A_N + B_N) return;

    float4 v;
    __nv_bfloat16 *dhi, *dlo;
    size_t o;
    if (idx < A_N) {
        int e = idx * 4, m = e >> 10, k = e & 1023;
        v = (k < 512) ? *(const float4*)(inputs + (size_t)m * 512 + k)
                      : *(const float4*)(hidden + (size_t)m * 512 + k - 512);
        dhi = g_Ahi; dlo = g_Alo; o = (size_t)e;
    } else {
        int t = idx - A_N, e = t * 4, n = e >> 10, k = e & 1023;
        v = (k < 512) ? *(const float4*)(W_ih + (size_t)n * 512 + k)
                      : *(const float4*)(W_hh + (size_t)n * 512 + k - 512);
        dhi = g_Bhi; dlo = g_Blo; o = (size_t)e;
    }
    float f[4] = {v.x, v.y, v.z, v.w};
    __nv_bfloat16 h[4], l[4];
    #pragma unroll
    for (int i = 0; i < 4; i++) {
        h[i] = __float2bfloat16(f[i]);
        l[i] = __float2bfloat16(f[i] - __bfloat162float(h[i]));
    }
    *(__nv_bfloat162*)(dhi + o)     = __nv_bfloat162(h[0], h[1]);
    *(__nv_bfloat162*)(dhi + o + 2) = __nv_bfloat162(h[2], h[3]);
    *(__nv_bfloat162*)(dlo + o)     = __nv_bfloat162(l[0], l[1]);
    *(__nv_bfloat162*)(dlo + o + 2) = __nv_bfloat162(l[2], l[3]);
}

// ---------------------------------------------------------------------------
// Kernel 1: HMMA bf16 split GEMM: proj[256,1536] = A[256,1024] @ B^T + bias
// CTA 64x64, 4 warps (2x2), warp tile 32x32, 32 K-chunks of 32, cp.async pipe.
// ---------------------------------------------------------------------------
#define AHI_OFF 0
#define ALO_OFF 4096
#define BHI_OFF 8192
#define BLO_OFF 12288
#define NCHUNK  32

__global__ __launch_bounds__(128) void gemm_mma_kernel(
    const float* __restrict__ b_ih, const float* __restrict__ b_hh)
{
    __shared__ __align__(1024) char smem[2][16384];
    __shared__ float sbias[64];

    const int tid = threadIdx.x;
    const int wid = tid >> 5, lane = tid & 31;
    const int wm = wid & 1, wn = wid >> 1;      // warp grid 2(m) x 2(n)
    const int bn = blockIdx.x * 64, bm = blockIdx.y * 64;

    if (tid < 64) sbias[tid] = b_ih[bn + tid] + b_hh[bn + tid];

    const uint32_t sb0 = smem_to_u32(&smem[0][0]);
    const uint32_t sb1 = smem_to_u32(&smem[1][0]);

    // per-thread load slots: 2 chunks of 16B per matrix per buffer fill
    const int c0row = tid >> 2,         c0chk = tid & 3;
    const int c1row = (tid + 128) >> 2, c1chk = (tid + 128) & 3;
    const uint32_t so0 = sw_off(c0row, c0chk);
    const uint32_t so1 = sw_off(c1row, c1chk);

    auto prefetch = [&](int ch) {
        const uint32_t sbuf = (ch & 1) ? sb1 : sb0;
        const int k0 = ch * 32;
        size_t gA0 = (size_t)(bm + c0row) * KTOT + k0 + c0chk * 8;
        size_t gA1 = (size_t)(bm + c1row) * KTOT + k0 + c1chk * 8;
        size_t gB0 = (size_t)(bn + c0row) * KTOT + k0 + c0chk * 8;
        size_t gB1 = (size_t)(bn + c1row) * KTOT + k0 + c1chk * 8;
        cp16(sbuf + AHI_OFF + so0, g_Ahi + gA0);
        cp16(sbuf + AHI_OFF + so1, g_Ahi + gA1);
        cp16(sbuf + ALO_OFF + so0, g_Alo + gA0);
        cp16(sbuf + ALO_OFF + so1, g_Alo + gA1);
        cp16(sbuf + BHI_OFF + so0, g_Bhi + gB0);
        cp16(sbuf + BHI_OFF + so1, g_Bhi + gB1);
        cp16(sbuf + BLO_OFF + so0, g_Blo + gB0);
        cp16(sbuf + BLO_OFF + so1, g_Blo + gB1);
        asm volatile("cp.async.commit_group;" ::: "memory");
    };

    float acc[2][4][4];
    #pragma unroll
    for (int mi = 0; mi < 2; mi++)
        #pragma unroll
        for (int ni = 0; ni < 4; ni++)
            #pragma unroll
            for (int q = 0; q < 4; q++) acc[mi][ni][q] = 0.0f;

    // lane-derived ldmatrix row/half (canonical x4 fragment addressing)
    const int lArow = wm * 32 + (lane & 15);
    const int lAhalf = lane >> 4;                           // k half
    const int lBrow = wn * 32 + ((lane >> 4) << 3) + (lane & 7);
    const int lBhalf = (lane >> 3) & 1;                     // k half

    prefetch(0);
    prefetch(1);

    for (int ch = 0; ch < NCHUNK; ch++) {
        if (ch < NCHUNK - 1) { asm volatile("cp.async.wait_group 1;" ::: "memory"); }
        else                 { asm volatile("cp.async.wait_group 0;" ::: "memory"); }
        __syncthreads();

        const uint32_t sbuf = (ch & 1) ? sb1 : sb0;

        #pragma unroll
        for (int ks = 0; ks < 2; ks++) {
            uint32_t ahi[2][4], alo[2][4], bhi[8], blo[8];
            #pragma unroll
            for (int mi = 0; mi < 2; mi++) {
                int row = lArow + mi * 16;
                uint32_t so = sw_off(row, ks * 2 + lAhalf);
                ldsm_x4(ahi[mi], sbuf + AHI_OFF + so);
                ldsm_x4(alo[mi], sbuf + ALO_OFF + so);
            }
            #pragma unroll
            for (int nj = 0; nj < 2; nj++) {
                int row = lBrow + nj * 16;
                uint32_t so = sw_off(row, ks * 2 + lBhalf);
                ldsm_x4(&bhi[nj * 4], sbuf + BHI_OFF + so);
                ldsm_x4(&blo[nj * 4], sbuf + BLO_OFF + so);
            }
            #pragma unroll
            for (int mi = 0; mi < 2; mi++)
                #pragma unroll
                for (int ni = 0; ni < 4; ni++) {
                    mma_bf16(acc[mi][ni], ahi[mi], &bhi[ni * 2]);
                    mma_bf16(acc[mi][ni], ahi[mi], &blo[ni * 2]);
                    mma_bf16(acc[mi][ni], alo[mi], &bhi[ni * 2]);
                }
        }
        __syncthreads();
        if (ch + 2 < NCHUNK) prefetch(ch + 2);
    }

    // Epilogue: += bias, write fp32 proj
    const int g = lane >> 2, tg = lane & 3;
    #pragma unroll
    for (int mi = 0; mi < 2; mi++) {
        #pragma unroll
        for (int ni = 0; ni < 4; ni++) {
            int colo = wn * 32 + ni * 8 + tg * 2;
            int col = bn + colo;
            float bv0 = sbias[colo], bv1 = sbias[colo + 1];
            int row0 = bm + wm * 32 + mi * 16 + g;
            float2 v0 = make_float2(acc[mi][ni][0] + bv0, acc[mi][ni][1] + bv1);
            float2 v1 = make_float2(acc[mi][ni][2] + bv0, acc[mi][ni][3] + bv1);
            *(float2*)(g_proj + (size_t)row0 * N3 + col) = v0;
            *(float2*)(g_proj + (size_t)(row0 + 8) * N3 + col) = v1;
        }
    }
}

// ---------------------------------------------------------------------------
// Kernel 2: per batch row: dot products -> alpha, beta;  Rh = h + a*x + b*r
// ---------------------------------------------------------------------------
__global__ __launch_bounds__(128) void vectors_kernel(const float* __restrict__ hidden)
{
    const int b = blockIdx.x, t = threadIdx.x;
    const float* base = g_proj + (size_t)b * N3;
    float4 x = ((const float4*)(base + 2 * Hd))[t];   // x_emb
    float4 r = ((const float4*)(base + Hd))[t];       // r
    float4 h = ((const float4*)(hidden + (size_t)b * Hd))[t];

    float vals[5];
    vals[0] = x.x * x.x + x.y * x.y + x.z * x.z + x.w * x.w;
    vals[1] = r.x * r.x + r.y * r.y + r.z * r.z + r.w * r.w;
    vals[2] = x.x * r.x + x.y * r.y + x.z * r.z + x.w * r.w;
    vals[3] = x.x * h.x + x.y * h.y + x.z * h.z + x.w * h.w;
    vals[4] = r.x * h.x + r.y * h.y + r.z * h.z + r.w * h.w;

    __shared__ float red[5][4];
    __shared__ float s_ab[2];
    int lane = t & 31, w = t >> 5;
    #pragma unroll
    for (int i = 0; i < 5; i++) {
        float v = vals[i];
        #pragma unroll
        for (int o = 16; o; o >>= 1) v += __shfl_down_sync(0xffffffffu, v, o);
        if (!lane) red[i][w] = v;
    }
    __syncthreads();
    if (t == 0) {
        float S[5];
        #pragma unroll
        for (int i = 0; i < 5; i++)
            S[i] = red[i][0] + red[i][1] + red[i][2] + red[i][3];
        const float eps = 1e-12f;
        float nx = fmaxf(sqrtf(S[0]), eps);
        float nr = fmaxf(sqrtf(S[1]), eps);
        float c  = S[2] / (nx * nr);
        float s  = sqrtf(fmaxf(1.0f - c * c, 0.0f));
        float g  = S[2] / (nx * nx);
        float vn2 = S[1] - 2.0f * g * S[2] + g * g * S[0];
        float nv = fmaxf(sqrtf(fmaxf(vn2, 0.0f)), eps);
        float uh = S[3] / nx;
        float vh = (S[4] - g * S[3]) / nv;
        float P = (c - 1.0f) * uh - s * vh;
        float Q = (c - 1.0f) * vh + s * uh;
        s_ab[0] = P / nx - Q * g / nv;
        s_ab[1] = Q / nv;
    }
    __syncthreads();
    float al = s_ab[0], be = s_ab[1];
    float4 o;
    o.x = h.x + al * x.x + be * r.x;
    o.y = h.y + al * x.y + be * r.y;
    o.z = h.z + al * x.z + be * r.z;
    o.w = h.w + al * x.w + be * r.w;
    ((float4*)(g_Rh + (size_t)b * Hd))[t] = o;
}

// ---------------------------------------------------------------------------
// Kernel 3: hn[b,i] = assoc[b,i,:] . Rh[b,:]   (HBM-bound, 256 MB single read)
// ---------------------------------------------------------------------------
__global__ __launch_bounds__(256) void matvec_kernel(const float* __restrict__ assoc)
{
    __shared__ float sRh[Hd];
    const int b = blockIdx.y;
    const int warp = threadIdx.x >> 5, lane = threadIdx.x & 31;

    for (int i = threadIdx.x; i < Hd; i += 256)
        sRh[i] = g_Rh[(size_t)b * Hd + i];
    __syncthreads();

    #pragma unroll
    for (int rr = 0; rr < 2; rr++) {
        int row = blockIdx.x * 16 + warp * 2 + rr;
        const float4* p = (const float4*)(assoc + ((size_t)b * Hd + row) * Hd);
        float sum = 0.0f;
        #pragma unroll
        for (int it = 0; it < 4; it++) {
            float4 v = p[lane + it * 32];
            int j = (lane + it * 32) << 2;
            sum += v.x * sRh[j] + v.y * sRh[j + 1] + v.z * sRh[j + 2] + v.w * sRh[j + 3];
        }
        #pragma unroll
        for (int o = 16; o; o >>= 1) sum += __shfl_down_sync(0xffffffffu, sum, o);
        if (!lane) g_hn[(size_t)b * Hd + row] = sum;
    }
}

// ---------------------------------------------------------------------------
// Kernel 4: pre = ug*h + (1-ug)*relu(hn + x);  out = pre / max(||pre||, eps)
// ---------------------------------------------------------------------------
__global__ __launch_bounds__(128) void finalize_kernel(
    const float* __restrict__ hidden, float* __restrict__ out)
{
    const int b = blockIdx.x, t = threadIdx.x;
    const float* base = g_proj + (size_t)b * N3;
    float4 ug = ((const float4*)base)[t];
    float4 x  = ((const float4*)(base + 2 * Hd))[t];
    float4 h  = ((const float4*)(hidden + (size_t)b * Hd))[t];
    float4 hn = ((const float4*)(g_hn + (size_t)b * Hd))[t];

    float4 pre;
    pre.x = ug.x * h.x + (1.0f - ug.x) * fmaxf(hn.x + x.x, 0.0f);
    pre.y = ug.y * h.y + (1.0f - ug.y) * fmaxf(hn.y + x.y, 0.0f);
    pre.z = ug.z * h.z + (1.0f - ug.z) * fmaxf(hn.z + x.z, 0.0f);
    pre.w = ug.w * h.w + (1.0f - ug.w) * fmaxf(hn.w + x.w, 0.0f);

    float ss = pre.x * pre.x + pre.y * pre.y + pre.z * pre.z + pre.w * pre.w;
    int lane = t & 31, w = t >> 5;
    #pragma unroll
    for (int o = 16; o; o >>= 1) ss += __shfl_down_sync(0xffffffffu, ss, o);
    __shared__ float red[4];
    __shared__ float s_inv;
    if (!lane) red[w] = ss;
    __syncthreads();
    if (t == 0) {
        float n = sqrtf(red[0] + red[1] + red[2] + red[3]);
        s_inv = 1.0f / fmaxf(n, 1e-12f);
    }
    __syncthreads();
    float inv = s_inv;
    float4 o4;
    o4.x = pre.x * inv; o4.y = pre.y * inv; o4.z = pre.z * inv; o4.w = pre.w * inv;
    ((float4*)out)[b * (Hd / 4) + t] = o4;
}

extern "C" void kernel_launch(void* const* d_in, const int* in_sizes, int n_in,
                              void* d_out, int out_size)
{
    const float* inputs = (const float*)d_in[0];
    const float* hidden = (const float*)d_in[1];
    const float* assoc  = (const float*)d_in[2];
    const float* W_ih   = (const float*)d_in[3];
    const float* b_ih   = (const float*)d_in[4];
    const float* W_hh   = (const float*)d_in[5];
    const float* b_hh   = (const float*)d_in[6];
    float* out = (float*)d_out;

    int conv_total = (Bsz * KTOT + N3 * KTOT) / 4;
    convert_kernel<<<(conv_total + 255) / 256, 256>>>(inputs, hidden, W_ih, W_hh);
    gemm_mma_kernel<<<dim3(N3 / 64, Bsz / 64), 128>>>(b_ih, b_hh);
    vectors_kernel<<<Bsz, 128>>>(hidden);
    matvec_kernel<<<dim3(Hd / 16, Bsz), 256>>>(assoc);
    finalize_kernel<<<Bsz, 128>>>(hidden, out);
}

// round 5
// speedup vs baseline: 1.5194x; 1.0262x over previous
#include <cuda_runtime.h>
#include <cuda_bf16.h>
#include <cstdint>

#define Bsz 256
#define Hd  512
#define N3  1536
#define KTOT 1024

// ---------------- scratch (no allocs allowed) ----------------
__device__ float g_proj[Bsz * N3];   // [B, 3H]: [u_gate | r | x_emb]
__device__ __nv_bfloat16 g_Ahi[Bsz * KTOT];
__device__ __nv_bfloat16 g_Alo[Bsz * KTOT];
__device__ __nv_bfloat16 g_Bhi[N3 * KTOT];
__device__ __nv_bfloat16 g_Blo[N3 * KTOT];

__device__ __forceinline__ uint32_t smem_to_u32(const void* p) {
    uint32_t a;
    asm("{ .reg .u64 t; cvta.to.shared.u64 t, %1; cvt.u32.u64 %0, t; }"
        : "=r"(a) : "l"(p));
    return a;
}
__device__ __forceinline__ void cp16(uint32_t s, const void* g) {
    asm volatile("cp.async.cg.shared.global [%0], [%1], 16;"
                 :: "r"(s), "l"(g) : "memory");
}
__device__ __forceinline__ void ldsm_x4(uint32_t* r, uint32_t addr) {
    asm volatile("ldmatrix.sync.aligned.m8n8.x4.shared.b16 {%0,%1,%2,%3}, [%4];"
                 : "=r"(r[0]), "=r"(r[1]), "=r"(r[2]), "=r"(r[3]) : "r"(addr));
}
__device__ __forceinline__ void mma_bf16(float* c, const uint32_t* a, const uint32_t* b) {
    asm volatile(
        "mma.sync.aligned.m16n8k16.row.col.f32.bf16.bf16.f32 "
        "{%0,%1,%2,%3}, {%4,%5,%6,%7}, {%8,%9}, {%0,%1,%2,%3};"
        : "+f"(c[0]), "+f"(c[1]), "+f"(c[2]), "+f"(c[3])
        : "r"(a[0]), "r"(a[1]), "r"(a[2]), "r"(a[3]), "r"(b[0]), "r"(b[1]));
}

// swizzled byte offset within a 64-row x 64-byte tile (4KB)
__device__ __forceinline__ uint32_t sw_off(int row, int chunk) {
    return (uint32_t)(row * 64 + ((chunk ^ ((row >> 1) & 3)) << 4));
}

// ---------------------------------------------------------------------------
// Kernel 0: fp32 -> (hi, lo) bf16 split of A=[inputs|hidden] and B=[W_ih|W_hh]
// ---------------------------------------------------------------------------
__global__ __launch_bounds__(256) void convert_kernel(
    const float* __restrict__ inputs, const float* __restrict__ hidden,
    const float* __restrict__ W_ih,   const float* __restrict__ W_hh)
{
    const int A_N = Bsz * KTOT / 4;          // 65536
    const int B_N = N3 * KTOT / 4;           // 393216
    int idx = blockIdx.x * blockDim.x + threadIdx.x;
    if (idx >= A_N + B_N) return;

    float4 v;
    __nv_bfloat16 *dhi, *dlo;
    size_t o;
    if (idx < A_N) {
        int e = idx * 4, m = e >> 10, k = e & 1023;
        v = (k < 512) ? *(const float4*)(inputs + (size_t)m * 512 + k)
                      : *(const float4*)(hidden + (size_t)m * 512 + k - 512);
        dhi = g_Ahi; dlo = g_Alo; o = (size_t)e;
    } else {
        int t = idx - A_N, e = t * 4, n = e >> 10, k = e & 1023;
        v = (k < 512) ? *(const float4*)(W_ih + (size_t)n * 512 + k)
                      : *(const float4*)(W_hh + (size_t)n * 512 + k - 512);
        dhi = g_Bhi; dlo = g_Blo; o = (size_t)e;
    }
    float f[4] = {v.x, v.y, v.z, v.w};
    __nv_bfloat16 h[4], l[4];
    #pragma unroll
    for (int i = 0; i < 4; i++) {
        h[i] = __float2bfloat16(f[i]);
        l[i] = __float2bfloat16(f[i] - __bfloat162float(h[i]));
    }
    *(__nv_bfloat162*)(dhi + o)     = __nv_bfloat162(h[0], h[1]);
    *(__nv_bfloat162*)(dhi + o + 2) = __nv_bfloat162(h[2], h[3]);
    *(__nv_bfloat162*)(dlo + o)     = __nv_bfloat162(l[0], l[1]);
    *(__nv_bfloat162*)(dlo + o + 2) = __nv_bfloat162(l[2], l[3]);
}

// ---------------------------------------------------------------------------
// Kernel 1: HMMA bf16 split GEMM: proj[256,1536] = A[256,1024] @ B^T + bias
// CTA 64x64, 4 warps (2x2), warp tile 32x32, 32 K-chunks of 32, cp.async pipe.
// ---------------------------------------------------------------------------
#define AHI_OFF 0
#define ALO_OFF 4096
#define BHI_OFF 8192
#define BLO_OFF 12288
#define NCHUNK  32

__global__ __launch_bounds__(128) void gemm_mma_kernel(
    const float* __restrict__ b_ih, const float* __restrict__ b_hh)
{
    __shared__ __align__(1024) char smem[2][16384];
    __shared__ float sbias[64];

    const int tid = threadIdx.x;
    const int wid = tid >> 5, lane = tid & 31;
    const int wm = wid & 1, wn = wid >> 1;      // warp grid 2(m) x 2(n)
    const int bn = blockIdx.x * 64, bm = blockIdx.y * 64;

    if (tid < 64) sbias[tid] = b_ih[bn + tid] + b_hh[bn + tid];

    const uint32_t sb0 = smem_to_u32(&smem[0][0]);
    const uint32_t sb1 = smem_to_u32(&smem[1][0]);

    const int c0row = tid >> 2,         c0chk = tid & 3;
    const int c1row = (tid + 128) >> 2, c1chk = (tid + 128) & 3;
    const uint32_t so0 = sw_off(c0row, c0chk);
    const uint32_t so1 = sw_off(c1row, c1chk);

    auto prefetch = [&](int ch) {
        const uint32_t sbuf = (ch & 1) ? sb1 : sb0;
        const int k0 = ch * 32;
        size_t gA0 = (size_t)(bm + c0row) * KTOT + k0 + c0chk * 8;
        size_t gA1 = (size_t)(bm + c1row) * KTOT + k0 + c1chk * 8;
        size_t gB0 = (size_t)(bn + c0row) * KTOT + k0 + c0chk * 8;
        size_t gB1 = (size_t)(bn + c1row) * KTOT + k0 + c1chk * 8;
        cp16(sbuf + AHI_OFF + so0, g_Ahi + gA0);
        cp16(sbuf + AHI_OFF + so1, g_Ahi + gA1);
        cp16(sbuf + ALO_OFF + so0, g_Alo + gA0);
        cp16(sbuf + ALO_OFF + so1, g_Alo + gA1);
        cp16(sbuf + BHI_OFF + so0, g_Bhi + gB0);
        cp16(sbuf + BHI_OFF + so1, g_Bhi + gB1);
        cp16(sbuf + BLO_OFF + so0, g_Blo + gB0);
        cp16(sbuf + BLO_OFF + so1, g_Blo + gB1);
        asm volatile("cp.async.commit_group;" ::: "memory");
    };

    float acc[2][4][4];
    #pragma unroll
    for (int mi = 0; mi < 2; mi++)
        #pragma unroll
        for (int ni = 0; ni < 4; ni++)
            #pragma unroll
            for (int q = 0; q < 4; q++) acc[mi][ni][q] = 0.0f;

    const int lArow = wm * 32 + (lane & 15);
    const int lAhalf = lane >> 4;
    const int lBrow = wn * 32 + ((lane >> 4) << 3) + (lane & 7);
    const int lBhalf = (lane >> 3) & 1;

    prefetch(0);
    prefetch(1);

    for (int ch = 0; ch < NCHUNK; ch++) {
        if (ch < NCHUNK - 1) { asm volatile("cp.async.wait_group 1;" ::: "memory"); }
        else                 { asm volatile("cp.async.wait_group 0;" ::: "memory"); }
        __syncthreads();

        const uint32_t sbuf = (ch & 1) ? sb1 : sb0;

        #pragma unroll
        for (int ks = 0; ks < 2; ks++) {
            uint32_t ahi[2][4], alo[2][4], bhi[8], blo[8];
            #pragma unroll
            for (int mi = 0; mi < 2; mi++) {
                int row = lArow + mi * 16;
                uint32_t so = sw_off(row, ks * 2 + lAhalf);
                ldsm_x4(ahi[mi], sbuf + AHI_OFF + so);
                ldsm_x4(alo[mi], sbuf + ALO_OFF + so);
            }
            #pragma unroll
            for (int nj = 0; nj < 2; nj++) {
                int row = lBrow + nj * 16;
                uint32_t so = sw_off(row, ks * 2 + lBhalf);
                ldsm_x4(&bhi[nj * 4], sbuf + BHI_OFF + so);
                ldsm_x4(&blo[nj * 4], sbuf + BLO_OFF + so);
            }
            #pragma unroll
            for (int mi = 0; mi < 2; mi++)
                #pragma unroll
                for (int ni = 0; ni < 4; ni++) {
                    mma_bf16(acc[mi][ni], ahi[mi], &bhi[ni * 2]);
                    mma_bf16(acc[mi][ni], ahi[mi], &blo[ni * 2]);
                    mma_bf16(acc[mi][ni], alo[mi], &bhi[ni * 2]);
                }
        }
        __syncthreads();
        if (ch + 2 < NCHUNK) prefetch(ch + 2);
    }

    const int g = lane >> 2, tg = lane & 3;
    #pragma unroll
    for (int mi = 0; mi < 2; mi++) {
        #pragma unroll
        for (int ni = 0; ni < 4; ni++) {
            int colo = wn * 32 + ni * 8 + tg * 2;
            int col = bn + colo;
            float bv0 = sbias[colo], bv1 = sbias[colo + 1];
            int row0 = bm + wm * 32 + mi * 16 + g;
            float2 v0 = make_float2(acc[mi][ni][0] + bv0, acc[mi][ni][1] + bv1);
            float2 v1 = make_float2(acc[mi][ni][2] + bv0, acc[mi][ni][3] + bv1);
            *(float2*)(g_proj + (size_t)row0 * N3 + col) = v0;
            *(float2*)(g_proj + (size_t)(row0 + 8) * N3 + col) = v1;
        }
    }
}

// ---------------------------------------------------------------------------
// Kernel 2 (FUSED): per batch row b (one 1024-thread CTA each):
//   phase 1: 5 dots -> alpha,beta; Rh = h + a*x + b*r  (smem)
//   phase 2: hn[i] = assoc[b,i,:] . Rh   (32 warps x 16 rows, __ldcs stream)
//   phase 3: pre = ug*h + (1-ug)*relu(hn + x); out = pre / max(||pre||,eps)
// ---------------------------------------------------------------------------
__global__ __launch_bounds__(1024) void fused_mv_kernel(
    const float* __restrict__ hidden, const float* __restrict__ assoc,
    float* __restrict__ out)
{
    __shared__ float sRh[Hd];
    __shared__ float s_hn[Hd];
    __shared__ float red[5][4];
    __shared__ float s_ab[2];
    __shared__ float nred[4];
    __shared__ float s_inv;

    const int b = blockIdx.x;
    const int t = threadIdx.x;
    const int lane = t & 31, warp = t >> 5;
    const float* base = g_proj + (size_t)b * N3;

    // ---- phase 1: dots (first 128 threads) ----
    if (t < 128) {
        float4 x = ((const float4*)(base + 2 * Hd))[t];
        float4 r = ((const float4*)(base + Hd))[t];
        float4 h = ((const float4*)(hidden + (size_t)b * Hd))[t];

        float vals[5];
        vals[0] = x.x * x.x + x.y * x.y + x.z * x.z + x.w * x.w;
        vals[1] = r.x * r.x + r.y * r.y + r.z * r.z + r.w * r.w;
        vals[2] = x.x * r.x + x.y * r.y + x.z * r.z + x.w * r.w;
        vals[3] = x.x * h.x + x.y * h.y + x.z * h.z + x.w * h.w;
        vals[4] = r.x * h.x + r.y * h.y + r.z * h.z + r.w * h.w;
        #pragma unroll
        for (int i = 0; i < 5; i++) {
            float v = vals[i];
            #pragma unroll
            for (int o = 16; o; o >>= 1) v += __shfl_down_sync(0xffffffffu, v, o);
            if (!lane) red[i][warp] = v;
        }
    }
    __syncthreads();
    if (t == 0) {
        float S[5];
        #pragma unroll
        for (int i = 0; i < 5; i++)
            S[i] = red[i][0] + red[i][1] + red[i][2] + red[i][3];
        const float eps = 1e-12f;
        float nx = fmaxf(sqrtf(S[0]), eps);
        float nr = fmaxf(sqrtf(S[1]), eps);
        float c  = S[2] / (nx * nr);
        float s  = sqrtf(fmaxf(1.0f - c * c, 0.0f));
        float g  = S[2] / (nx * nx);
        float vn2 = S[1] - 2.0f * g * S[2] + g * g * S[0];
        float nv = fmaxf(sqrtf(fmaxf(vn2, 0.0f)), eps);
        float uh = S[3] / nx;
        float vh = (S[4] - g * S[3]) / nv;
        float P = (c - 1.0f) * uh - s * vh;
        float Q = (c - 1.0f) * vh + s * uh;
        s_ab[0] = P / nx - Q * g / nv;
        s_ab[1] = Q / nv;
    }
    __syncthreads();
    if (t < 128) {
        float4 x = ((const float4*)(base + 2 * Hd))[t];
        float4 r = ((const float4*)(base + Hd))[t];
        float4 h = ((const float4*)(hidden + (size_t)b * Hd))[t];
        float al = s_ab[0], be = s_ab[1];
        float4 o;
        o.x = h.x + al * x.x + be * r.x;
        o.y = h.y + al * x.y + be * r.y;
        o.z = h.z + al * x.z + be * r.z;
        o.w = h.w + al * x.w + be * r.w;
        ((float4*)sRh)[t] = o;
    }
    __syncthreads();

    // ---- phase 2: matvec, 32 warps x 16 rows, streaming loads ----
    #pragma unroll 1
    for (int rr = 0; rr < 16; rr++) {
        int row = warp * 16 + rr;
        const float4* p = (const float4*)(assoc + ((size_t)b * Hd + row) * Hd);
        float sum = 0.0f;
        #pragma unroll
        for (int it = 0; it < 4; it++) {
            float4 v = __ldcs(p + lane + it * 32);
            int j = (lane + it * 32) << 2;
            sum += v.x * sRh[j] + v.y * sRh[j + 1] + v.z * sRh[j + 2] + v.w * sRh[j + 3];
        }
        #pragma unroll
        for (int o = 16; o; o >>= 1) sum += __shfl_down_sync(0xffffffffu, sum, o);
        if (!lane) s_hn[row] = sum;
    }
    __syncthreads();

    // ---- phase 3: finalize (first 128 threads) ----
    float4 pre;
    if (t < 128) {
        float4 ug = ((const float4*)base)[t];
        float4 x  = ((const float4*)(base + 2 * Hd))[t];
        float4 h  = ((const float4*)(hidden + (size_t)b * Hd))[t];
        float4 hn = ((const float4*)s_hn)[t];
        pre.x = ug.x * h.x + (1.0f - ug.x) * fmaxf(hn.x + x.x, 0.0f);
        pre.y = ug.y * h.y + (1.0f - ug.y) * fmaxf(hn.y + x.y, 0.0f);
        pre.z = ug.z * h.z + (1.0f - ug.z) * fmaxf(hn.z + x.z, 0.0f);
        pre.w = ug.w * h.w + (1.0f - ug.w) * fmaxf(hn.w + x.w, 0.0f);
        float ss = pre.x * pre.x + pre.y * pre.y + pre.z * pre.z + pre.w * pre.w;
        #pragma unroll
        for (int o = 16; o; o >>= 1) ss += __shfl_down_sync(0xffffffffu, ss, o);
        if (!lane) nred[warp] = ss;
    }
    __syncthreads();
    if (t == 0) {
        float n = sqrtf(nred[0] + nred[1] + nred[2] + nred[3]);
        s_inv = 1.0f / fmaxf(n, 1e-12f);
    }
    __syncthreads();
    if (t < 128) {
        float inv = s_inv;
        float4 o4;
        o4.x = pre.x * inv; o4.y = pre.y * inv;
        o4.z = pre.z * inv; o4.w = pre.w * inv;
        ((float4*)out)[b * (Hd / 4) + t] = o4;
    }
}

extern "C" void kernel_launch(void* const* d_in, const int* in_sizes, int n_in,
                              void* d_out, int out_size)
{
    const float* inputs = (const float*)d_in[0];
    const float* hidden = (const float*)d_in[1];
    const float* assoc  = (const float*)d_in[2];
    const float* W_ih   = (const float*)d_in[3];
    const float* b_ih   = (const float*)d_in[4];
    const float* W_hh   = (const float*)d_in[5];
    const float* b_hh   = (const float*)d_in[6];
    float* out = (float*)d_out;

    int conv_total = (Bsz * KTOT + N3 * KTOT) / 4;
    convert_kernel<<<(conv_total + 255) / 256, 256>>>(inputs, hidden, W_ih, W_hh);
    gemm_mma_kernel<<<dim3(N3 / 64, Bsz / 64), 128>>>(b_ih, b_hh);
    fused_mv_kernel<<<Bsz, 1024>>>(hidden, assoc, out);
}